// round 1
// baseline (speedup 1.0000x reference)
#include <cuda_runtime.h>
#include <math.h>

#define NCLS   20
#define GRIDW  38
#define NCELL  1444          // 38*38
#define NANC   5
#define NBOX   16
#define BATCH  64
#define CSTRIDE 180500       // 125 * 1444 floats per batch
#define EPS16  0.0009765625f // 2^-10

__constant__ float c_anc[NANC][2] = {
    {0.05f, 0.07f}, {0.12f, 0.15f}, {0.25f, 0.30f}, {0.45f, 0.55f}, {0.75f, 0.80f}
};

// accumulators: 0=S_conf_pos 1=S_neg_marked 2=S_cls 3=S_txty 4=S_twth
//               5=S_neg_all  6=sum 1/nums_pos_b  7=sum 1/nums_neg_b
__device__ float g_acc[8];
__device__ int   g_npos;

__device__ __forceinline__ float sigmoid_clip(float x) {
    float p = 1.0f / (1.0f + __expf(-x));
    return fminf(fmaxf(p, EPS16), 1.0f - EPS16);
}

// f(x) for the negative conf loss: -0.5 * p^2 * log(1-p), p = clip(sigmoid(x))
__device__ __forceinline__ float fneg(float x) {
    float p = sigmoid_clip(x);
    return -0.5f * p * p * __logf(1.0f - p);
}

__global__ void k_init() {
    if (threadIdx.x < 8) g_acc[threadIdx.x] = 0.0f;
    if (threadIdx.x == 8) g_npos = 0;
}

// One block (1 warp) per batch: matching + all sparse (positive) loss terms +
// marked-cell negative-sum subtraction.
__global__ void k_match(const float* __restrict__ py,
                        const float* __restrict__ gb,
                        const int*   __restrict__ gl) {
    const int b    = blockIdx.x;
    const int lane = threadIdx.x;

    __shared__ int   s_key[NBOX], s_cell[NBOX], s_anc[NBOX], s_lab[NBOX];
    __shared__ float s_tx[NBOX], s_ty[NBOX], s_twx[NBOX], s_twy[NBOX], s_wpos[NBOX];

    if (lane < NBOX) {
        const float* bp = gb + (b * NBOX + lane) * 4;
        float l = bp[0], t = bp[1], r = bp[2], d = bp[3];
        float cx = (l + r) * 0.5f, cy = (t + d) * 0.5f;
        float w  = r - l,          h  = d - t;

        // argmax IoU over anchors (first max on ties, like jnp.argmax)
        int bi = 0; float best = -1.0f;
        #pragma unroll
        for (int a = 0; a < NANC; a++) {
            float aw = c_anc[a][0], ah = c_anc[a][1];
            float inter = fminf(w, aw) * fminf(h, ah);
            float un    = w * h + aw * ah - inter;
            float iou   = inter / un;
            if (iou > best) { best = iou; bi = a; }
        }
        int col = (int)floorf(cx * GRIDW); col = min(max(col, 0), GRIDW - 1);
        int row = (int)floorf(cy * GRIDW); row = min(max(row, 0), GRIDW - 1);
        int cell = row * GRIDW + col;

        s_cell[lane] = cell;
        s_anc[lane]  = bi;
        s_key[lane]  = cell * NANC + bi;
        s_lab[lane]  = gl[b * NBOX + lane] - 1;
        s_tx[lane]   = cx * GRIDW - (float)col;
        s_ty[lane]   = cy * GRIDW - (float)row;
        s_twx[lane]  = __logf(w / c_anc[bi][0]);
        s_twy[lane]  = __logf(h / c_anc[bi][1]);
        s_wpos[lane] = l;  // reference uses gy[...,26] = gboxes left coord (index bug kept)
    }
    __syncwarp();

    // live = last occurrence of key (scatter last-write-wins)
    // first = first occurrence of cell (for marked-cell set)
    int live = 0, first = 0;
    if (lane < NBOX) {
        live = 1;
        for (int j = lane + 1; j < NBOX; j++)
            if (s_key[j] == s_key[lane]) { live = 0; break; }
        first = 1;
        for (int j = 0; j < lane; j++)
            if (s_cell[j] == s_cell[lane]) { first = 0; break; }
    }
    unsigned mlive  = __ballot_sync(0xffffffffu, live);
    unsigned mfirst = __ballot_sync(0xffffffffu, first);
    int npos   = __popc(mlive);
    int ncellm = __popc(mfirst);
    float nneg = (float)(NANC * NCELL - NANC * ncellm);

    float a_conf = 0.f, a_cls = 0.f, a_txy = 0.f, a_twh = 0.f, a_sub = 0.f;
    const float* base = py + (long long)b * CSTRIDE;

    if (lane < NBOX && live) {
        int cell = s_cell[lane], anc = s_anc[lane], lab = s_lab[lane];

        // conf (positive): -0.5*(1-p)^2*log(p)
        float p = sigmoid_clip(base[anc * NCELL + cell]);
        float om = 1.0f - p;
        a_conf = -0.5f * om * om * __logf(p);

        // class BCE over 20 classes, target = onehot(lab)
        #pragma unroll 4
        for (int f = 1; f <= NCLS; f++) {
            float pc = sigmoid_clip(base[(f * NANC + anc) * NCELL + cell]);
            float g  = (f - 1 == lab) ? 1.0f : 0.0f;
            a_cls += -(g * __logf(pc) + (1.0f - g) * __logf(1.0f - pc));
        }

        float wpos = s_wpos[lane];
        // txty BCE
        float ptx = sigmoid_clip(base[(21 * NANC + anc) * NCELL + cell]);
        float pty = sigmoid_clip(base[(22 * NANC + anc) * NCELL + cell]);
        float gx = s_tx[lane], gy = s_ty[lane];
        float bcex = -(gx * __logf(ptx) + (1.0f - gx) * __logf(1.0f - ptx));
        float bcey = -(gy * __logf(pty) + (1.0f - gy) * __logf(1.0f - pty));
        a_txy = (bcex + bcey) * wpos;

        // twth L2 (raw logits, no sigmoid)
        float dx = base[(23 * NANC + anc) * NCELL + cell] - s_twx[lane];
        float dy = base[(24 * NANC + anc) * NCELL + cell] - s_twy[lane];
        a_twh = (dx * dx + dy * dy) * wpos;
    }

    // subtract marked-cell anchors from dense negative sum (gconf != 0 there)
    for (int k = lane; k < NBOX * NANC; k += 32) {
        int i = k / NANC, a = k % NANC;
        if ((mfirst >> i) & 1u)
            a_sub += fneg(base[a * NCELL + s_cell[i]]);
    }

    #pragma unroll
    for (int off = 16; off; off >>= 1) {
        a_conf += __shfl_down_sync(0xffffffffu, a_conf, off);
        a_cls  += __shfl_down_sync(0xffffffffu, a_cls,  off);
        a_txy  += __shfl_down_sync(0xffffffffu, a_txy,  off);
        a_twh  += __shfl_down_sync(0xffffffffu, a_twh,  off);
        a_sub  += __shfl_down_sync(0xffffffffu, a_sub,  off);
    }
    if (lane == 0) {
        atomicAdd(&g_acc[0], a_conf);
        atomicAdd(&g_acc[1], a_sub);
        atomicAdd(&g_acc[2], a_cls);
        atomicAdd(&g_acc[3], a_txy);
        atomicAdd(&g_acc[4], a_twh);
        atomicAdd(&g_acc[6], 1.0f / fmaxf((float)npos, EPS16));
        atomicAdd(&g_acc[7], 1.0f / fmaxf(nneg, EPS16));
        atomicAdd(&g_npos, npos);
    }
}

// Dense negative-conf sum over all 64*5*1444 anchors (conf planes are the
// first 7220 floats of each batch chunk; 7220 % 4 == 0 -> float4 loads).
__global__ void k_neg(const float* __restrict__ py) {
    const int TOT4   = BATCH * NANC * NCELL / 4;  // 115520
    const int PER_B4 = NANC * NCELL / 4;          // 1805
    const int CS4    = CSTRIDE / 4;               // 45125
    const float4* p4 = reinterpret_cast<const float4*>(py);

    float acc = 0.0f;
    for (int q = blockIdx.x * blockDim.x + threadIdx.x; q < TOT4;
         q += gridDim.x * blockDim.x) {
        int b = q / PER_B4;
        int r = q - b * PER_B4;
        float4 v = p4[(long long)b * CS4 + r];
        acc += fneg(v.x) + fneg(v.y) + fneg(v.z) + fneg(v.w);
    }

    __shared__ float sh[8];
    float s = acc;
    #pragma unroll
    for (int off = 16; off; off >>= 1) s += __shfl_down_sync(0xffffffffu, s, off);
    int w = threadIdx.x >> 5, l = threadIdx.x & 31;
    if (l == 0) sh[w] = s;
    __syncthreads();
    if (w == 0) {
        s = (l < (blockDim.x >> 5)) ? sh[l] : 0.0f;
        #pragma unroll
        for (int off = 4; off; off >>= 1) s += __shfl_down_sync(0xffffffffu, s, off);
        if (l == 0) atomicAdd(&g_acc[5], s);
    }
}

__global__ void k_fin(float* out) {
    float npos_tot = fmaxf((float)g_npos, 1.0f);
    float sneg = g_acc[5] - g_acc[1];
    float loss = g_acc[0] * (g_acc[6] * (1.0f / BATCH))          // l_conf_pos
               + 3.0f * sneg * (g_acc[7] * (1.0f / BATCH))       // l_conf_neg
               + (g_acc[2] + g_acc[3] + g_acc[4]) / npos_tot;    // l_cls + l_txty + l_twth
    out[0] = loss;
}

extern "C" void kernel_launch(void* const* d_in, const int* in_sizes, int n_in,
                              void* d_out, int out_size) {
    const float* py = (const float*)d_in[0];
    const float* gb = (const float*)d_in[1];
    const int*   gl = (const int*)d_in[2];
    float* out = (float*)d_out;

    k_init<<<1, 32>>>();
    k_match<<<BATCH, 32>>>(py, gb, gl);
    k_neg<<<452, 256>>>(py);
    k_fin<<<1, 1>>>(out);
}

// round 2
// speedup vs baseline: 1.5013x; 1.5013x over previous
#include <cuda_runtime.h>
#include <math.h>

#define NCLS   20
#define GRIDW  38
#define NCELL  1444          // 38*38
#define NANC   5
#define NBOX   16
#define BATCH  64
#define CSTRIDE 180500       // 125 * 1444 floats per batch
#define EPS16  0.0009765625f // 2^-10
#define NBLOCKS 452

__constant__ float c_anc[NANC][2] = {
    {0.05f, 0.07f}, {0.12f, 0.15f}, {0.25f, 0.30f}, {0.45f, 0.55f}, {0.75f, 0.80f}
};

// accumulators: 0=S_conf_pos 1=S_neg_marked 2=S_cls 3=S_txty 4=S_twth
//               5=S_neg_all  6=sum 1/nums_pos_b  7=sum 1/nums_neg_b
__device__ float    g_acc[8];   // zero at module load; finalize re-zeros after use
__device__ int      g_npos;
__device__ unsigned g_cnt;

__device__ __forceinline__ float htanh(float x) {
    float t;
    asm("tanh.approx.f32 %0, %1;" : "=f"(t) : "f"(x));
    return t;
}

__device__ __forceinline__ float sigmoid_clip(float x) {
    float t = htanh(0.5f * x);
    float p = 0.5f + 0.5f * t;                       // sigmoid(x), no rcp
    return fminf(fmaxf(p, EPS16), 1.0f - EPS16);
}

// negative conf loss: -0.5 * p^2 * log(1-p), p = clip(sigmoid(x))
// 2 MUFU ops: tanh + lg2 (1-p computed cancellation-free as (1-t)/2)
__device__ __forceinline__ float fneg(float x) {
    float t = htanh(0.5f * x);
    float p = fminf(fmaxf(0.5f + 0.5f * t, EPS16), 1.0f - EPS16);
    float q = fminf(fmaxf(0.5f - 0.5f * t, EPS16), 1.0f - EPS16);
    return -0.5f * p * p * __logf(q);
}

__global__ void __launch_bounds__(256, 8)
k_fused(const float* __restrict__ py,
        const float* __restrict__ gb,
        const int*   __restrict__ gl,
        float* __restrict__ out) {
    // ---------- sparse part: blocks 0..63, warp 0 = matching + positive terms ----------
    if (blockIdx.x < BATCH && threadIdx.x < 32) {
        const int b    = blockIdx.x;
        const int lane = threadIdx.x;

        __shared__ int   s_cell[NBOX], s_anc[NBOX];
        __shared__ float s_tx[NBOX], s_ty[NBOX], s_twx[NBOX], s_twy[NBOX], s_wpos[NBOX];
        int my_key = -1, my_lab = 0;

        if (lane < NBOX) {
            const float* bp = gb + (b * NBOX + lane) * 4;
            float l = bp[0], t = bp[1], r = bp[2], d = bp[3];
            float cx = (l + r) * 0.5f, cy = (t + d) * 0.5f;
            float w  = r - l,          h  = d - t;

            int bi = 0; float best = -1.0f;
            #pragma unroll
            for (int a = 0; a < NANC; a++) {
                float aw = c_anc[a][0], ah = c_anc[a][1];
                float inter = fminf(w, aw) * fminf(h, ah);
                float un    = w * h + aw * ah - inter;
                float iou   = inter / un;
                if (iou > best) { best = iou; bi = a; }
            }
            int col = (int)floorf(cx * GRIDW); col = min(max(col, 0), GRIDW - 1);
            int row = (int)floorf(cy * GRIDW); row = min(max(row, 0), GRIDW - 1);
            int cell = row * GRIDW + col;

            s_cell[lane] = cell;
            s_anc[lane]  = bi;
            my_key       = cell * NANC + bi;
            my_lab       = gl[b * NBOX + lane] - 1;
            s_tx[lane]   = cx * GRIDW - (float)col;
            s_ty[lane]   = cy * GRIDW - (float)row;
            s_twx[lane]  = __logf(w / c_anc[bi][0]);
            s_twy[lane]  = __logf(h / c_anc[bi][1]);
            s_wpos[lane] = l;  // replicates reference index bug: gy[...,26] = left coord
        }
        __syncwarp();

        // live = last occurrence of key (scatter last-write-wins)
        // first = first occurrence of cell (marked-cell set)
        int live = 0, first = 0;
        if (lane < NBOX) {
            live = 1;
            for (int j = lane + 1; j < NBOX; j++)
                if (s_cell[j] * NANC + s_anc[j] == my_key) { live = 0; break; }
            first = 1;
            for (int j = 0; j < lane; j++)
                if (s_cell[j] == s_cell[lane]) { first = 0; break; }
        }
        unsigned mlive  = __ballot_sync(0xffffffffu, live);
        unsigned mfirst = __ballot_sync(0xffffffffu, first);
        int npos   = __popc(mlive);
        int ncellm = __popc(mfirst);
        float nneg = (float)(NANC * NCELL - NANC * ncellm);

        float a_conf = 0.f, a_cls = 0.f, a_txy = 0.f, a_twh = 0.f, a_sub = 0.f;
        const float* base = py + (long long)b * CSTRIDE;

        if (lane < NBOX && live) {
            int cell = s_cell[lane], anc = s_anc[lane], lab = my_lab;

            float p = sigmoid_clip(base[anc * NCELL + cell]);
            float om = 1.0f - p;
            a_conf = -0.5f * om * om * __logf(p);

            #pragma unroll 4
            for (int f = 1; f <= NCLS; f++) {
                float pc = sigmoid_clip(base[(f * NANC + anc) * NCELL + cell]);
                float g  = (f - 1 == lab) ? 1.0f : 0.0f;
                a_cls += -(g * __logf(pc) + (1.0f - g) * __logf(1.0f - pc));
            }

            float wpos = s_wpos[lane];
            float ptx = sigmoid_clip(base[(21 * NANC + anc) * NCELL + cell]);
            float pty = sigmoid_clip(base[(22 * NANC + anc) * NCELL + cell]);
            float gx = s_tx[lane], gy = s_ty[lane];
            float bcex = -(gx * __logf(ptx) + (1.0f - gx) * __logf(1.0f - ptx));
            float bcey = -(gy * __logf(pty) + (1.0f - gy) * __logf(1.0f - pty));
            a_txy = (bcex + bcey) * wpos;

            float dx = base[(23 * NANC + anc) * NCELL + cell] - s_twx[lane];
            float dy = base[(24 * NANC + anc) * NCELL + cell] - s_twy[lane];
            a_twh = (dx * dx + dy * dy) * wpos;
        }

        // subtract marked-cell anchors (same fneg as the dense path!)
        for (int k = lane; k < NBOX * NANC; k += 32) {
            int i = k / NANC, a = k % NANC;
            if ((mfirst >> i) & 1u)
                a_sub += fneg(base[a * NCELL + s_cell[i]]);
        }

        #pragma unroll
        for (int off = 16; off; off >>= 1) {
            a_conf += __shfl_down_sync(0xffffffffu, a_conf, off);
            a_cls  += __shfl_down_sync(0xffffffffu, a_cls,  off);
            a_txy  += __shfl_down_sync(0xffffffffu, a_txy,  off);
            a_twh  += __shfl_down_sync(0xffffffffu, a_twh,  off);
            a_sub  += __shfl_down_sync(0xffffffffu, a_sub,  off);
        }
        if (lane == 0) {
            atomicAdd(&g_acc[0], a_conf);
            atomicAdd(&g_acc[1], a_sub);
            atomicAdd(&g_acc[2], a_cls);
            atomicAdd(&g_acc[3], a_txy);
            atomicAdd(&g_acc[4], a_twh);
            atomicAdd(&g_acc[6], 1.0f / fmaxf((float)npos, EPS16));
            atomicAdd(&g_acc[7], 1.0f / fmaxf(nneg, EPS16));
            atomicAdd(&g_npos, npos);
        }
    }

    // ---------- dense part: all blocks, grid-stride over conf planes ----------
    {
        const int TOT4   = BATCH * NANC * NCELL / 4;  // 115520
        const int PER_B4 = NANC * NCELL / 4;          // 1805
        const int CS4    = CSTRIDE / 4;               // 45125
        const float4* p4 = reinterpret_cast<const float4*>(py);

        float acc = 0.0f;
        for (int q = blockIdx.x * blockDim.x + threadIdx.x; q < TOT4;
             q += gridDim.x * blockDim.x) {
            int b = q / PER_B4;
            int r = q - b * PER_B4;
            float4 v = p4[(long long)b * CS4 + r];
            acc += fneg(v.x) + fneg(v.y) + fneg(v.z) + fneg(v.w);
        }

        __shared__ float sh[8];
        float s = acc;
        #pragma unroll
        for (int off = 16; off; off >>= 1) s += __shfl_down_sync(0xffffffffu, s, off);
        int w = threadIdx.x >> 5, l = threadIdx.x & 31;
        if (l == 0) sh[w] = s;
        __syncthreads();
        if (w == 0) {
            s = (l < (blockDim.x >> 5)) ? sh[l] : 0.0f;
            #pragma unroll
            for (int off = 4; off; off >>= 1) s += __shfl_down_sync(0xffffffffu, s, off);
            if (l == 0) atomicAdd(&g_acc[5], s);
        }
    }

    // ---------- finalize: last block computes the scalar and resets state ----------
    __threadfence();
    __shared__ int isLast;
    if (threadIdx.x == 0) {
        unsigned v = atomicAdd(&g_cnt, 1u);
        isLast = (v == gridDim.x - 1);
    }
    __syncthreads();
    if (isLast && threadIdx.x == 0) {
        float npos_tot = fmaxf((float)g_npos, 1.0f);
        float sneg = g_acc[5] - g_acc[1];
        float loss = g_acc[0] * (g_acc[6] * (1.0f / BATCH))          // l_conf_pos
                   + 3.0f * sneg * (g_acc[7] * (1.0f / BATCH))       // l_conf_neg
                   + (g_acc[2] + g_acc[3] + g_acc[4]) / npos_tot;    // l_cls+l_txty+l_twth
        out[0] = loss;
        // reset for next graph replay
        #pragma unroll
        for (int i = 0; i < 8; i++) g_acc[i] = 0.0f;
        g_npos = 0;
        g_cnt  = 0;
    }
}

extern "C" void kernel_launch(void* const* d_in, const int* in_sizes, int n_in,
                              void* d_out, int out_size) {
    const float* py = (const float*)d_in[0];
    const float* gb = (const float*)d_in[1];
    const int*   gl = (const int*)d_in[2];
    float* out = (float*)d_out;

    k_fused<<<NBLOCKS, 256>>>(py, gb, gl, out);
}